// round 2
// baseline (speedup 1.0000x reference)
#include <cuda_runtime.h>
#include <cstdint>
#include <math.h>

#define N_NODES 100000
#define N_EDGES 3200000
#define D_FEAT  512
#define HID     16

#define SCAN_BLOCKS 100
#define SCAN_ELEMS  1000   // SCAN_BLOCKS * SCAN_ELEMS = N_NODES

// ---------------- scratch (device globals; no allocation allowed) ----------
__device__ float g_t1[N_NODES * HID];   // x @ W1
__device__ float g_h1[N_NODES * HID];   // layer-1 aggregated output
__device__ float g_t2[N_NODES * HID];   // relu(h1+b1) @ W2
__device__ int   g_cnt[N_NODES];        // in-degree per node
__device__ int   g_cur[N_NODES];        // fill cursor per node
__device__ int   g_off[N_NODES];        // CSR offsets (exclusive scan of cnt)
__device__ int   g_bsum[SCAN_BLOCKS];   // per-block sums for scan
__device__ int2  g_adj[N_EDGES];        // packed {src, weight_bits} grouped by dst
__device__ int   g_is64;

// ---------------- helpers --------------------------------------------------
__device__ __forceinline__ unsigned long long ffma2(unsigned long long a,
                                                    unsigned long long b,
                                                    unsigned long long c) {
    unsigned long long d;
    asm("fma.rn.f32x2 %0, %1, %2, %3;" : "=l"(d) : "l"(a), "l"(b), "l"(c));
    return d;
}

// ---------------- edge_index dtype detection (parallel) --------------------
// If int64 with values in [0, N_NODES), every high 32-bit word is 0.
__global__ void detect_kernel(const void* eiv) {
    __shared__ int any32;
    if (threadIdx.x == 0) any32 = 0;
    __syncthreads();
    const int* p = (const int*)eiv;
    int local = 0;
    for (int i = threadIdx.x; i < 2048; i += 256)
        if (p[2 * i + 1] != 0) local = 1;
    if (local) atomicOr(&any32, 1);
    __syncthreads();
    if (threadIdx.x == 0) g_is64 = !any32;
}

// ---------------- zero counters -------------------------------------------
__global__ void zero_cnt_kernel() {
    int i = blockIdx.x * blockDim.x + threadIdx.x;
    if (i < N_NODES) { g_cnt[i] = 0; g_cur[i] = 0; }
}

// ---------------- histogram of dst ----------------------------------------
__global__ void hist_kernel(const void* __restrict__ eiv) {
    int e = blockIdx.x * blockDim.x + threadIdx.x;
    if (e >= N_EDGES) return;
    int d;
    if (g_is64) d = (int)((const long long*)eiv)[N_EDGES + e];
    else        d = ((const int*)eiv)[N_EDGES + e];
    atomicAdd(&g_cnt[d], 1);
}

// ---------------- prefix scan: phase 1 (per-block sums) --------------------
__global__ void scan1_kernel() {
    __shared__ int sh[1024];
    int b = blockIdx.x, t = threadIdx.x;
    int v = (t < SCAN_ELEMS) ? g_cnt[b * SCAN_ELEMS + t] : 0;
    sh[t] = v;
    __syncthreads();
    for (int s = 512; s > 0; s >>= 1) {
        if (t < s) sh[t] += sh[t + s];
        __syncthreads();
    }
    if (t == 0) g_bsum[b] = sh[0];
}

// ---------------- prefix scan: phase 2 (exclusive scan of block sums) ------
__global__ void scan2_kernel() {
    __shared__ int sh[SCAN_BLOCKS];
    int t = threadIdx.x;
    if (t < SCAN_BLOCKS) sh[t] = g_bsum[t];
    __syncthreads();
    if (t == 0) {
        int run = 0;
        for (int i = 0; i < SCAN_BLOCKS; i++) {
            int v = sh[i]; sh[i] = run; run += v;
        }
    }
    __syncthreads();
    if (t < SCAN_BLOCKS) g_bsum[t] = sh[t];
}

// ---------------- prefix scan: phase 3 (intra-block scan + offset) ---------
__global__ void scan3_kernel() {
    __shared__ int sh[1024];
    int b = blockIdx.x, t = threadIdx.x;
    int myv = (t < SCAN_ELEMS) ? g_cnt[b * SCAN_ELEMS + t] : 0;
    sh[t] = myv;
    __syncthreads();
    // Hillis-Steele inclusive scan over 1024
    for (int s = 1; s < 1024; s <<= 1) {
        int v = (t >= s) ? sh[t - s] : 0;
        __syncthreads();
        sh[t] += v;
        __syncthreads();
    }
    if (t < SCAN_ELEMS)
        g_off[b * SCAN_ELEMS + t] = sh[t] - myv + g_bsum[b];
}

// ---------------- fill CSR adjacency ---------------------------------------
__global__ void fill_kernel(const void* __restrict__ eiv,
                            const float* __restrict__ ew) {
    int e = blockIdx.x * blockDim.x + threadIdx.x;
    if (e >= N_EDGES) return;
    int s, d;
    if (g_is64) {
        s = (int)((const long long*)eiv)[e];
        d = (int)((const long long*)eiv)[N_EDGES + e];
    } else {
        s = ((const int*)eiv)[e];
        d = ((const int*)eiv)[N_EDGES + e];
    }
    float w = ew[e];
    int pos = g_off[d] + atomicAdd(&g_cur[d], 1);
    g_adj[pos] = make_int2(s, __float_as_int(w));
}

// ---------------- GEMM1: t1 = x @ W1  (100000x512 @ 512x16) ---------------
#define KT 8
__global__ void gemm1_kernel(const float* __restrict__ x,
                             const float* __restrict__ W1) {
    __shared__ float Ws[D_FEAT * HID];       // 32 KB
    __shared__ float xs[256 * (KT + 1)];     // 9 KB, pad stride 9

    const int t = threadIdx.x;
    for (int i = t; i < D_FEAT * HID; i += 256) Ws[i] = W1[i];

    const int row0   = blockIdx.x * 256;
    const int my_row = row0 + t;

    unsigned long long acc[8];
#pragma unroll
    for (int j = 0; j < 8; j++) acc[j] = 0ULL;

    for (int kt = 0; kt < D_FEAT / KT; kt++) {
        const int k0 = kt * KT;
        __syncthreads();
#pragma unroll
        for (int i = 0; i < KT; i++) {
            int idx = t + 256 * i;
            int r = idx >> 3;
            int kk = idx & 7;
            int gr = row0 + r;
            xs[r * (KT + 1) + kk] =
                (gr < N_NODES) ? x[(size_t)gr * D_FEAT + k0 + kk] : 0.0f;
        }
        __syncthreads();

        const float* xrow = xs + t * (KT + 1);
#pragma unroll
        for (int kk = 0; kk < KT; kk++) {
            float xv = xrow[kk];
            unsigned long long xp;
            unsigned int xb = __float_as_uint(xv);
            asm("mov.b64 %0, {%1, %1};" : "=l"(xp) : "r"(xb));
            const ulonglong2* wrow =
                (const ulonglong2*)(Ws + (k0 + kk) * HID);
#pragma unroll
            for (int j2 = 0; j2 < 4; j2++) {
                ulonglong2 wp = wrow[j2];
                acc[2 * j2]     = ffma2(xp, wp.x, acc[2 * j2]);
                acc[2 * j2 + 1] = ffma2(xp, wp.y, acc[2 * j2 + 1]);
            }
        }
    }

    if (my_row < N_NODES) {
        float o[16];
#pragma unroll
        for (int j = 0; j < 8; j++) {
            unsigned int lo, hi;
            asm("mov.b64 {%0, %1}, %2;" : "=r"(lo), "=r"(hi) : "l"(acc[j]));
            o[2 * j]     = __uint_as_float(lo);
            o[2 * j + 1] = __uint_as_float(hi);
        }
        float4* dst = (float4*)(g_t1 + (size_t)my_row * HID);
        dst[0] = make_float4(o[0], o[1], o[2], o[3]);
        dst[1] = make_float4(o[4], o[5], o[6], o[7]);
        dst[2] = make_float4(o[8], o[9], o[10], o[11]);
        dst[3] = make_float4(o[12], o[13], o[14], o[15]);
    }
}

// ---------------- atomic-free gather: acc[n] = sum_e w_e * feat[src_e] -----
// 4 threads per node, each owns a float4 column chunk.
__global__ void gather_kernel(float* __restrict__ out, int pass) {
    int u = blockIdx.x * blockDim.x + threadIdx.x;
    if (u >= N_NODES * 4) return;
    int node = u >> 2;
    int c = u & 3;

    const float* feat = (pass == 0) ? g_t1 : g_t2;
    float*       acc  = (pass == 0) ? g_h1 : out;

    int beg = g_off[node];
    int deg = g_cnt[node];

    float4 s = make_float4(0.f, 0.f, 0.f, 0.f);
    for (int i = 0; i < deg; i++) {
        int2 e = g_adj[beg + i];
        float w = __int_as_float(e.y);
        float4 v = *(const float4*)(feat + (size_t)e.x * HID + c * 4);
        s.x = fmaf(w, v.x, s.x);
        s.y = fmaf(w, v.y, s.y);
        s.z = fmaf(w, v.z, s.z);
        s.w = fmaf(w, v.w, s.w);
    }
    *(float4*)(acc + (size_t)node * HID + c * 4) = s;
}

// ---------------- mid: t2 = relu(h1 + b1) @ W2 -----------------------------
__global__ void mid_kernel(const float* __restrict__ b1,
                           const float* __restrict__ W2) {
    __shared__ float W2s[HID * HID];
    __shared__ float b1s[HID];
    int t = threadIdx.x;
    if (t < HID * HID) W2s[t] = W2[t];
    if (t < HID) b1s[t] = b1[t];
    __syncthreads();

    int node = blockIdx.x * blockDim.x + t;
    if (node >= N_NODES) return;

    float v[16];
    const float4* src = (const float4*)(g_h1 + (size_t)node * HID);
#pragma unroll
    for (int q = 0; q < 4; q++) {
        float4 f = src[q];
        v[4 * q] = f.x; v[4 * q + 1] = f.y; v[4 * q + 2] = f.z; v[4 * q + 3] = f.w;
    }
#pragma unroll
    for (int i = 0; i < 16; i++) v[i] = fmaxf(v[i] + b1s[i], 0.0f);

    float o[16];
#pragma unroll
    for (int j = 0; j < 16; j++) o[j] = 0.0f;
#pragma unroll
    for (int i = 0; i < 16; i++) {
        float vi = v[i];
#pragma unroll
        for (int j = 0; j < 16; j++) o[j] = fmaf(vi, W2s[i * 16 + j], o[j]);
    }

    float4* dst = (float4*)(g_t2 + (size_t)node * HID);
    dst[0] = make_float4(o[0], o[1], o[2], o[3]);
    dst[1] = make_float4(o[4], o[5], o[6], o[7]);
    dst[2] = make_float4(o[8], o[9], o[10], o[11]);
    dst[3] = make_float4(o[12], o[13], o[14], o[15]);
}

// ---------------- final: out = log_softmax(out + b2) -----------------------
__global__ void final_kernel(float* __restrict__ out,
                             const float* __restrict__ b2) {
    __shared__ float b2s[HID];
    if (threadIdx.x < HID) b2s[threadIdx.x] = b2[threadIdx.x];
    __syncthreads();

    int node = blockIdx.x * blockDim.x + threadIdx.x;
    if (node >= N_NODES) return;

    float o[16];
    float4* p = (float4*)(out + (size_t)node * HID);
#pragma unroll
    for (int q = 0; q < 4; q++) {
        float4 f = p[q];
        o[4 * q]     = f.x + b2s[4 * q];
        o[4 * q + 1] = f.y + b2s[4 * q + 1];
        o[4 * q + 2] = f.z + b2s[4 * q + 2];
        o[4 * q + 3] = f.w + b2s[4 * q + 3];
    }
    float m = o[0];
#pragma unroll
    for (int j = 1; j < 16; j++) m = fmaxf(m, o[j]);
    float ssum = 0.0f;
#pragma unroll
    for (int j = 0; j < 16; j++) ssum += expf(o[j] - m);
    float lse = m + logf(ssum);
#pragma unroll
    for (int j = 0; j < 16; j++) o[j] -= lse;

    p[0] = make_float4(o[0], o[1], o[2], o[3]);
    p[1] = make_float4(o[4], o[5], o[6], o[7]);
    p[2] = make_float4(o[8], o[9], o[10], o[11]);
    p[3] = make_float4(o[12], o[13], o[14], o[15]);
}

// ---------------- launch ---------------------------------------------------
extern "C" void kernel_launch(void* const* d_in, const int* in_sizes, int n_in,
                              void* d_out, int out_size) {
    const float* x  = (const float*)d_in[0];
    const void*  ei = d_in[1];
    const float* ew = (const float*)d_in[2];
    const float* W1 = (const float*)d_in[3];
    const float* b1 = (const float*)d_in[4];
    const float* W2 = (const float*)d_in[5];
    const float* b2 = (const float*)d_in[6];
    float* out = (float*)d_out;

    const int eb = (N_EDGES + 255) / 256;

    detect_kernel<<<1, 256>>>(ei);
    zero_cnt_kernel<<<(N_NODES + 255) / 256, 256>>>();
    hist_kernel<<<eb, 256>>>(ei);
    scan1_kernel<<<SCAN_BLOCKS, 1024>>>();
    scan2_kernel<<<1, 128>>>();
    scan3_kernel<<<SCAN_BLOCKS, 1024>>>();
    fill_kernel<<<eb, 256>>>(ei, ew);

    gemm1_kernel<<<(N_NODES + 255) / 256, 256>>>(x, W1);

    const int gb = (N_NODES * 4 + 255) / 256;
    gather_kernel<<<gb, 256>>>(out, 0);
    mid_kernel<<<(N_NODES + 255) / 256, 256>>>(b1, W2);
    gather_kernel<<<gb, 256>>>(out, 1);
    final_kernel<<<(N_NODES + 255) / 256, 256>>>(b2 ? out : out, b2);
}